// round 8
// baseline (speedup 1.0000x reference)
#include <cuda_runtime.h>
#include <cstdint>

#define NN 512
#define LUT_N 83521            // 17^4
#define NPIX (4 * NN * NN)

// ---------------- device scratch ----------------
__device__ int8_t g_q0[3 * LUT_N];        // stage-0 quantized LUT (int8)
__device__ uint4  g_q1[3 * LUT_N];        // stage-1 quantized LUT (16 ch, biased u8, 16B/row)
__device__ float  g_x1[NPIX];             // stage-0 output image (integers 0..255)

__constant__ float c_samp0[108];
__constant__ float c_samp1[108];
__constant__ float c_sb0[12];
__constant__ float c_sb1[12];
__constant__ float c_resw[12];

// ---------------- f32x2 helpers ----------------
__device__ __forceinline__ unsigned long long pack2(unsigned lo, unsigned hi) {
    unsigned long long d;
    asm("mov.b64 %0, {%1, %2};" : "=l"(d) : "r"(lo), "r"(hi));
    return d;
}
__device__ __forceinline__ unsigned long long pack2f(float lo, float hi) {
    return pack2(__float_as_uint(lo), __float_as_uint(hi));
}
__device__ __forceinline__ void unpack2(unsigned long long v, float& lo, float& hi) {
    asm("mov.b64 {%0, %1}, %2;" : "=f"(lo), "=f"(hi) : "l"(v));
}
__device__ __forceinline__ unsigned long long fadd2(unsigned long long a, unsigned long long b) {
    unsigned long long d;
    asm("add.rn.f32x2 %0, %1, %2;" : "=l"(d) : "l"(a), "l"(b));
    return d;
}
__device__ __forceinline__ unsigned long long ffma2(unsigned long long a, unsigned long long b,
                                                    unsigned long long c) {
    unsigned long long d;
    asm("fma.rn.f32x2 %0, %1, %2, %3;" : "=l"(d) : "l"(a), "l"(b), "l"(c));
    return d;
}

// ---------------- LUT quantization ----------------
__global__ void quant_lut0(const float* __restrict__ src) {
    int i = blockIdx.x * blockDim.x + threadIdx.x;
    if (i < 3 * LUT_N) {
        float q = rintf(src[i] * 127.0f);
        q = fminf(fmaxf(q, -127.0f), 127.0f);
        g_q0[i] = (int8_t)(int)q;
    }
}

__global__ void quant_lut1(const float* __restrict__ src) {
    int i = blockIdx.x * blockDim.x + threadIdx.x;
    if (i < 3 * LUT_N) {
        const float* s = src + (size_t)i * 16;
        unsigned w[4];
#pragma unroll
        for (int wi = 0; wi < 4; wi++) {
            unsigned acc = 0;
#pragma unroll
            for (int b = 0; b < 4; b++) {
                float q = rintf(s[wi * 4 + b] * 127.0f);
                q = fminf(fmaxf(q, -127.0f), 127.0f);
                unsigned v = (unsigned)((int)q + 128);   // biased u8
                acc |= v << (b * 8);
            }
            w[wi] = acc;
        }
        g_q1[i] = make_uint4(w[0], w[1], w[2], w[3]);
    }
}

// ---------------- helpers ----------------
// Rotation-r tap position in the 5x5 neighborhood.
// r=0: X[p+u,q+v]; r=1: X[p+v,q-u]; r=2: X[p-u,q-v]; r=3: X[p-v,q+u]
__device__ __forceinline__ constexpr int nb_idx(int R, int u, int w) {
    int dy = (R == 0) ? u : (R == 1) ? w : (R == 2) ? -u : -w;
    int dx = (R == 0) ? w : (R == 1) ? -u : (R == 2) ? -w : u;
    return (2 + dy) * 5 + (2 + dx);
}

// 4D simplex; ws pre-scaled by 1/16 (exact)
__device__ __forceinline__ void simplex(const float v[4], int verts[5], float ws[5]) {
    int la = (int)(v[0] * 0.0625f), lb = (int)(v[1] * 0.0625f);
    int lc = (int)(v[2] * 0.0625f), ld = (int)(v[3] * 0.0625f);
    float f0 = v[0] - 16.0f * la, f1 = v[1] - 16.0f * lb;
    float f2 = v[2] - 16.0f * lc, f3 = v[3] - 16.0f * ld;
    int base = la * 4913 + lb * 289 + lc * 17 + ld;
    int t0 = 4913, t1 = 289, t2 = 17, t3 = 1;
#define CSW(fa_, fb_, ta_, tb_)                         \
    { if (fa_ < fb_) { float tf = fa_; fa_ = fb_; fb_ = tf; \
                       int ti = ta_; ta_ = tb_; tb_ = ti; } }
    CSW(f0, f1, t0, t1); CSW(f2, f3, t2, t3);
    CSW(f0, f2, t0, t2); CSW(f1, f3, t1, t3);
    CSW(f1, f2, t1, t2);
#undef CSW
    ws[0] = (16.0f - f0) * 0.0625f;
    ws[1] = (f0 - f1) * 0.0625f;
    ws[2] = (f1 - f2) * 0.0625f;
    ws[3] = (f2 - f3) * 0.0625f;
    ws[4] = f3 * 0.0625f;
    verts[0] = base;
    verts[1] = verts[0] + t0;
    verts[2] = verts[1] + t1;
    verts[3] = verts[2] + t2;
    verts[4] = verts[3] + t3;
}

// ---------------- stage 0 (unchanged from R7) ----------------
__global__ void __launch_bounds__(256, 3) stage0_kernel(const float* __restrict__ x) {
    int q = blockIdx.x * 32 + threadIdx.x;
    int p = blockIdx.y * 8 + threadIdx.y;
    int b = blockIdx.z;

    unsigned long long pkA[9], pkB[9];   // (R0,R2) and (R1,R3) packed taps
    {
        const float* img = x + (size_t)b * NN * NN;
        float nb[25];
        int rr[5], cc[5];
#pragma unroll
        for (int i = 0; i < 5; i++) {
            rr[i] = min(max(p - 2 + i, 0), NN - 1);
            cc[i] = min(max(q - 2 + i, 0), NN - 1);
        }
#pragma unroll
        for (int i = 0; i < 5; i++)
#pragma unroll
            for (int j = 0; j < 5; j++)
                nb[i * 5 + j] = 255.0f * __ldg(img + rr[i] * NN + cc[j]);
#pragma unroll
        for (int u = 0; u < 3; u++)
#pragma unroll
            for (int w = 0; w < 3; w++) {
                int iA = nb_idx(0, u, w);
                int iB = nb_idx(1, u, w);
                pkA[u * 3 + w] = pack2f(nb[iA], nb[24 - iA]);
                pkB[u * 3 + w] = pack2f(nb[iB], nb[24 - iB]);
            }
    }

    float total = 0.0f;
#pragma unroll
    for (int s = 0; s < 3; s++) {
        const float* wg = c_samp0 + s * 36;
        const float* bi = c_sb0 + s * 4;
        const int8_t* lt = g_q0 + s * LUT_N;

        float v[4][4];
#pragma unroll
        for (int ch = 0; ch < 4; ch++) {
            float bv = bi[ch];
            unsigned long long accA = pack2f(bv, bv);
            unsigned long long accB = accA;
#pragma unroll
            for (int t = 0; t < 9; t++) {
                float wv = wg[ch * 9 + t];
                unsigned long long w2 = pack2f(wv, wv);
                accA = ffma2(w2, pkA[t], accA);
                accB = ffma2(w2, pkB[t], accB);
            }
            unpack2(accA, v[0][ch], v[2][ch]);
            unpack2(accB, v[1][ch], v[3][ch]);
        }

        float acc = 0.0f;
#pragma unroll
        for (int R = 0; R < 4; R++) {
            int verts[5]; float ws[5];
            simplex(v[R], verts, ws);
            float dot = 0.0f;
#pragma unroll
            for (int t = 0; t < 5; t++) dot += ws[t] * (float)__ldg(lt + verts[t]);
            acc = rintf(acc + dot);
        }
        total += acc;
    }
    float o = rintf(fminf(fmaxf(total * (1.0f / 12.0f) + 127.0f, 0.0f), 255.0f));
    g_x1[(size_t)b * NN * NN + p * NN + q] = o;
}

// ---------------- stage 1 ----------------
// Rotation-outer processing: each rotation reads only its 3x3 quadrant (18 tap regs).
// blk[k] accumulates rintf(c_{s,R}[k]) — order-free since accumulator stays integer.
template <int R>
__device__ __forceinline__ void do_rot1(const float* __restrict__ img1,
                                        const float* __restrict__ img0,
                                        const int rr[5], const int cc[5],
                                        float blk[16]) {
    // load this rotation's 3x3 quadrant taps (coalesced, L1-hot)
    float tc[9], tp[9];
#pragma unroll
    for (int u = 0; u < 3; u++)
#pragma unroll
        for (int w = 0; w < 3; w++) {
            const int fi = nb_idx(R, u, w);
            const int iy = fi / 5, ix = fi % 5;
            int off = rr[iy] * NN + cc[ix];
            tc[u * 3 + w] = __ldg(img1 + off);
            tp[u * 3 + w] = 255.0f * __ldg(img0 + off);
        }

#pragma unroll
    for (int s = 0; s < 3; s++) {
        const float* wg = c_samp1 + s * 36;
        const float* bi = c_sb1 + s * 4;
        const uint4* lt = g_q1 + s * LUT_N;

        // scalar conv: cur + prev share weights, then residual blend
        float v[4];
#pragma unroll
        for (int ch = 0; ch < 4; ch++) {
            float a = bi[ch], bprev = bi[ch];
#pragma unroll
            for (int t = 0; t < 9; t++) {
                float wv = wg[ch * 9 + t];
                a = fmaf(wv, tc[t], a);
                bprev = fmaf(wv, tp[t], bprev);
            }
            float rwc = fminf(fmaxf(c_resw[s * 4 + ch], 0.0f), 1.0f);
            v[ch] = a + rwc * (bprev - a);
        }

        int vt[5]; float ws[5];
        simplex(v, vt, ws);

        uint4 d[5];
#pragma unroll
        for (int t = 0; t < 5; t++) d[t] = __ldg(lt + vt[t]);

        unsigned long long c2[8];
#pragma unroll
        for (int pidx = 0; pidx < 8; pidx++) c2[pidx] = 0ull;
        const unsigned long long B2 = pack2(0xCB000080u, 0xCB000080u);  // (-8388736,-8388736)

#pragma unroll
        for (int t = 0; t < 5; t++) {
            unsigned wtb = __float_as_uint(ws[t]);
            unsigned long long wt2 = pack2(wtb, wtb);
#pragma unroll
            for (int pidx = 0; pidx < 8; pidx++) {
                unsigned word = (pidx < 2) ? d[t].x : (pidx < 4) ? d[t].y
                              : (pidx < 6) ? d[t].z : d[t].w;
                int kk = (pidx & 1) * 2;
                unsigned lo = __byte_perm(word, 0x4B000000u, 0x7540u + kk);
                unsigned hi = __byte_perm(word, 0x4B000000u, 0x7541u + kk);
                unsigned long long m2 = fadd2(pack2(lo, hi), B2);  // exact (byte-128)
                c2[pidx] = ffma2(m2, wt2, c2[pidx]);
            }
        }

        float c[16];
#pragma unroll
        for (int pidx = 0; pidx < 8; pidx++) unpack2(c2[pidx], c[2 * pidx], c[2 * pidx + 1]);

#pragma unroll
        for (int i = 0; i < 4; i++)
#pragma unroll
            for (int j = 0; j < 4; j++) {
                int k = (R == 0) ? (i * 4 + j)
                      : (R == 1) ? ((3 - j) * 4 + i)
                      : (R == 2) ? ((3 - i) * 4 + (3 - j))
                                 : (j * 4 + (3 - i));
                blk[i * 4 + j] += rintf(c[k]);   // exact integer adds
            }
    }
}

__global__ void __launch_bounds__(128, 5) stage1_kernel(const float* __restrict__ x,
                                                        float* __restrict__ out) {
    int q = blockIdx.x * 32 + threadIdx.x;
    int p = blockIdx.y * 4 + threadIdx.y;
    int b = blockIdx.z;

    const float* img1 = g_x1 + (size_t)b * NN * NN;
    const float* img0 = x + (size_t)b * NN * NN;
    int rr[5], cc[5];
#pragma unroll
    for (int i = 0; i < 5; i++) {
        rr[i] = min(max(p - 2 + i, 0), NN - 1);
        cc[i] = min(max(q - 2 + i, 0), NN - 1);
    }

    float blk[16];
#pragma unroll
    for (int k = 0; k < 16; k++) blk[k] = 0.0f;

    do_rot1<0>(img1, img0, rr, cc, blk);
    do_rot1<1>(img1, img0, rr, cc, blk);
    do_rot1<2>(img1, img0, rr, cc, blk);
    do_rot1<3>(img1, img0, rr, cc, blk);

    float* op = out + ((size_t)b << 22) + (size_t)(4 * p) * 2048 + 4 * q;
#pragma unroll
    for (int i = 0; i < 4; i++) {
        float4 o;
        o.x = rintf(fminf(fmaxf(blk[i * 4 + 0] * (1.0f / 3.0f), 0.0f), 255.0f)) * (1.0f / 255.0f);
        o.y = rintf(fminf(fmaxf(blk[i * 4 + 1] * (1.0f / 3.0f), 0.0f), 255.0f)) * (1.0f / 255.0f);
        o.z = rintf(fminf(fmaxf(blk[i * 4 + 2] * (1.0f / 3.0f), 0.0f), 255.0f)) * (1.0f / 255.0f);
        o.w = rintf(fminf(fmaxf(blk[i * 4 + 3] * (1.0f / 3.0f), 0.0f), 255.0f)) * (1.0f / 255.0f);
        *reinterpret_cast<float4*>(op + (size_t)i * 2048) = o;
    }
}

// ---------------- launch ----------------
extern "C" void kernel_launch(void* const* d_in, const int* in_sizes, int n_in,
                              void* d_out, int out_size) {
    const float* x     = (const float*)d_in[0];
    const float* lut0  = (const float*)d_in[1];
    const float* lut1  = (const float*)d_in[2];
    const float* samp0 = (const float*)d_in[3];
    const float* samp1 = (const float*)d_in[4];
    const float* sb0   = (const float*)d_in[5];
    const float* sb1   = (const float*)d_in[6];
    const float* resw  = (const float*)d_in[7];

    cudaMemcpyToSymbolAsync(c_samp0, samp0, 108 * sizeof(float), 0, cudaMemcpyDeviceToDevice);
    cudaMemcpyToSymbolAsync(c_samp1, samp1, 108 * sizeof(float), 0, cudaMemcpyDeviceToDevice);
    cudaMemcpyToSymbolAsync(c_sb0,   sb0,    12 * sizeof(float), 0, cudaMemcpyDeviceToDevice);
    cudaMemcpyToSymbolAsync(c_sb1,   sb1,    12 * sizeof(float), 0, cudaMemcpyDeviceToDevice);
    cudaMemcpyToSymbolAsync(c_resw,  resw,   12 * sizeof(float), 0, cudaMemcpyDeviceToDevice);

    int nlut = 3 * LUT_N;
    quant_lut0<<<(nlut + 255) / 256, 256>>>(lut0);
    quant_lut1<<<(nlut + 255) / 256, 256>>>(lut1);

    dim3 blk0(32, 8, 1);
    dim3 grd0(NN / 32, NN / 8, 4);
    stage0_kernel<<<grd0, blk0>>>(x);

    dim3 blk1(32, 4, 1);
    dim3 grd1(NN / 32, NN / 4, 4);
    stage1_kernel<<<grd1, blk1>>>(x, (float*)d_out);
}

// round 9
// speedup vs baseline: 1.1064x; 1.1064x over previous
#include <cuda_runtime.h>
#include <cstdint>

#define NN 512
#define LUT_N 83521            // 17^4
#define NPIX (4 * NN * NN)

// ---------------- device scratch ----------------
__device__ int8_t g_q0[3 * LUT_N];        // stage-0 quantized LUT (int8)
__device__ uint4  g_q1[3 * LUT_N];        // stage-1 quantized LUT (16 ch, biased u8, 16B/row)
__device__ float  g_x1[NPIX];             // stage-0 output image (integers 0..255)

__constant__ float c_samp0[108];
__constant__ float c_samp1[108];
__constant__ float c_sb0[12];
__constant__ float c_sb1[12];
__constant__ float c_resw[12];

// ---------------- f32x2 helpers ----------------
__device__ __forceinline__ unsigned long long pack2(unsigned lo, unsigned hi) {
    unsigned long long d;
    asm("mov.b64 %0, {%1, %2};" : "=l"(d) : "r"(lo), "r"(hi));
    return d;
}
__device__ __forceinline__ unsigned long long pack2f(float lo, float hi) {
    return pack2(__float_as_uint(lo), __float_as_uint(hi));
}
__device__ __forceinline__ void unpack2(unsigned long long v, float& lo, float& hi) {
    asm("mov.b64 {%0, %1}, %2;" : "=f"(lo), "=f"(hi) : "l"(v));
}
__device__ __forceinline__ unsigned long long fadd2(unsigned long long a, unsigned long long b) {
    unsigned long long d;
    asm("add.rn.f32x2 %0, %1, %2;" : "=l"(d) : "l"(a), "l"(b));
    return d;
}
__device__ __forceinline__ unsigned long long ffma2(unsigned long long a, unsigned long long b,
                                                    unsigned long long c) {
    unsigned long long d;
    asm("fma.rn.f32x2 %0, %1, %2, %3;" : "=l"(d) : "l"(a), "l"(b), "l"(c));
    return d;
}

// ---------------- LUT quantization ----------------
__global__ void quant_lut0(const float* __restrict__ src) {
    int i = blockIdx.x * blockDim.x + threadIdx.x;
    if (i < 3 * LUT_N) {
        float q = rintf(src[i] * 127.0f);
        q = fminf(fmaxf(q, -127.0f), 127.0f);
        g_q0[i] = (int8_t)(int)q;
    }
}

__device__ __forceinline__ unsigned q1_byte(float v) {
    float q = rintf(v * 127.0f);
    q = fminf(fmaxf(q, -127.0f), 127.0f);
    return (unsigned)((int)q + 128);   // biased u8
}

// word-per-thread: coalesced float4 reads, coalesced u32 writes
__global__ void quant_lut1(const float* __restrict__ src) {
    int i = blockIdx.x * blockDim.x + threadIdx.x;   // output word index
    if (i < 3 * LUT_N * 4) {
        float4 f = reinterpret_cast<const float4*>(src)[i];
        unsigned acc = q1_byte(f.x) | (q1_byte(f.y) << 8)
                     | (q1_byte(f.z) << 16) | (q1_byte(f.w) << 24);
        reinterpret_cast<unsigned*>(g_q1)[i] = acc;
    }
}

// ---------------- helpers ----------------
// Rotation-r tap position in the 5x5 neighborhood.
// r=0: X[p+u,q+v]; r=1: X[p+v,q-u]; r=2: X[p-u,q-v]; r=3: X[p-v,q+u]
__device__ __forceinline__ constexpr int nb_idx(int R, int u, int w) {
    int dy = (R == 0) ? u : (R == 1) ? w : (R == 2) ? -u : -w;
    int dx = (R == 0) ? w : (R == 1) ? -u : (R == 2) ? -w : u;
    return (2 + dy) * 5 + (2 + dx);
}

// 4D simplex; ws pre-scaled by 1/16 (exact)
__device__ __forceinline__ void simplex(const float v[4], int verts[5], float ws[5]) {
    int la = (int)(v[0] * 0.0625f), lb = (int)(v[1] * 0.0625f);
    int lc = (int)(v[2] * 0.0625f), ld = (int)(v[3] * 0.0625f);
    float f0 = v[0] - 16.0f * la, f1 = v[1] - 16.0f * lb;
    float f2 = v[2] - 16.0f * lc, f3 = v[3] - 16.0f * ld;
    int base = la * 4913 + lb * 289 + lc * 17 + ld;
    int t0 = 4913, t1 = 289, t2 = 17, t3 = 1;
#define CSW(fa_, fb_, ta_, tb_)                         \
    { if (fa_ < fb_) { float tf = fa_; fa_ = fb_; fb_ = tf; \
                       int ti = ta_; ta_ = tb_; tb_ = ti; } }
    CSW(f0, f1, t0, t1); CSW(f2, f3, t2, t3);
    CSW(f0, f2, t0, t2); CSW(f1, f3, t1, t3);
    CSW(f1, f2, t1, t2);
#undef CSW
    ws[0] = (16.0f - f0) * 0.0625f;
    ws[1] = (f0 - f1) * 0.0625f;
    ws[2] = (f1 - f2) * 0.0625f;
    ws[3] = (f2 - f3) * 0.0625f;
    ws[4] = f3 * 0.0625f;
    verts[0] = base;
    verts[1] = verts[0] + t0;
    verts[2] = verts[1] + t1;
    verts[3] = verts[2] + t2;
    verts[4] = verts[3] + t3;
}

// ---------------- stage 0 (best-known, unchanged) ----------------
__global__ void __launch_bounds__(256, 3) stage0_kernel(const float* __restrict__ x) {
    int q = blockIdx.x * 32 + threadIdx.x;
    int p = blockIdx.y * 8 + threadIdx.y;
    int b = blockIdx.z;

    unsigned long long pkA[9], pkB[9];   // (R0,R2) and (R1,R3) packed taps
    {
        const float* img = x + (size_t)b * NN * NN;
        float nb[25];
        int rr[5], cc[5];
#pragma unroll
        for (int i = 0; i < 5; i++) {
            rr[i] = min(max(p - 2 + i, 0), NN - 1);
            cc[i] = min(max(q - 2 + i, 0), NN - 1);
        }
#pragma unroll
        for (int i = 0; i < 5; i++)
#pragma unroll
            for (int j = 0; j < 5; j++)
                nb[i * 5 + j] = 255.0f * __ldg(img + rr[i] * NN + cc[j]);
#pragma unroll
        for (int u = 0; u < 3; u++)
#pragma unroll
            for (int w = 0; w < 3; w++) {
                int iA = nb_idx(0, u, w);
                int iB = nb_idx(1, u, w);
                pkA[u * 3 + w] = pack2f(nb[iA], nb[24 - iA]);
                pkB[u * 3 + w] = pack2f(nb[iB], nb[24 - iB]);
            }
    }

    float total = 0.0f;
#pragma unroll
    for (int s = 0; s < 3; s++) {
        const float* wg = c_samp0 + s * 36;
        const float* bi = c_sb0 + s * 4;
        const int8_t* lt = g_q0 + s * LUT_N;

        float v[4][4];
#pragma unroll
        for (int ch = 0; ch < 4; ch++) {
            float bv = bi[ch];
            unsigned long long accA = pack2f(bv, bv);
            unsigned long long accB = accA;
#pragma unroll
            for (int t = 0; t < 9; t++) {
                float wv = wg[ch * 9 + t];
                unsigned long long w2 = pack2f(wv, wv);
                accA = ffma2(w2, pkA[t], accA);
                accB = ffma2(w2, pkB[t], accB);
            }
            unpack2(accA, v[0][ch], v[2][ch]);
            unpack2(accB, v[1][ch], v[3][ch]);
        }

        float acc = 0.0f;
#pragma unroll
        for (int R = 0; R < 4; R++) {
            int verts[5]; float ws[5];
            simplex(v[R], verts, ws);
            float dot = 0.0f;
#pragma unroll
            for (int t = 0; t < 5; t++) dot += ws[t] * (float)__ldg(lt + verts[t]);
            acc = rintf(acc + dot);
        }
        total += acc;
    }
    float o = rintf(fminf(fmaxf(total * (1.0f / 12.0f) + 127.0f, 0.0f), 255.0f));
    g_x1[(size_t)b * NN * NN + p * NN + q] = o;
}

// ---------------- stage 1 ----------------
// fused per-rotation: simplex + gather + accumulate; blk[k] += rintf(c[k]) (exact,
// order-free: every term is integer-valued after rintf)
template <int R>
__device__ __forceinline__ void proc_rot1(const float v[4], const uint4* __restrict__ lt,
                                          float blk[16]) {
    int vt[5]; float ws[5];
    simplex(v, vt, ws);

    uint4 d[5];
#pragma unroll
    for (int t = 0; t < 5; t++) d[t] = __ldg(lt + vt[t]);

    unsigned long long c2[8];
#pragma unroll
    for (int pidx = 0; pidx < 8; pidx++) c2[pidx] = 0ull;
    const unsigned long long B2 = pack2(0xCB000080u, 0xCB000080u);  // (-8388736,-8388736)

#pragma unroll
    for (int t = 0; t < 5; t++) {
        unsigned wtb = __float_as_uint(ws[t]);
        unsigned long long wt2 = pack2(wtb, wtb);
#pragma unroll
        for (int pidx = 0; pidx < 8; pidx++) {
            unsigned word = (pidx < 2) ? d[t].x : (pidx < 4) ? d[t].y
                          : (pidx < 6) ? d[t].z : d[t].w;
            int kk = (pidx & 1) * 2;
            unsigned lo = __byte_perm(word, 0x4B000000u, 0x7540u + kk);
            unsigned hi = __byte_perm(word, 0x4B000000u, 0x7541u + kk);
            unsigned long long m2 = fadd2(pack2(lo, hi), B2);  // exact (byte-128)
            c2[pidx] = ffma2(m2, wt2, c2[pidx]);
        }
    }

    float c[16];
#pragma unroll
    for (int pidx = 0; pidx < 8; pidx++) unpack2(c2[pidx], c[2 * pidx], c[2 * pidx + 1]);

#pragma unroll
    for (int i = 0; i < 4; i++)
#pragma unroll
        for (int j = 0; j < 4; j++) {
            int k = (R == 0) ? (i * 4 + j)
                  : (R == 1) ? ((3 - j) * 4 + i)
                  : (R == 2) ? ((3 - i) * 4 + (3 - j))
                             : (j * 4 + (3 - i));
            blk[i * 4 + j] += rintf(c[k]);
        }
}

__global__ void __launch_bounds__(256, 2) stage1_kernel(const float* __restrict__ x,
                                                        float* __restrict__ out) {
    int q = blockIdx.x * 32 + threadIdx.x;
    int p = blockIdx.y * 8 + threadIdx.y;
    int b = blockIdx.z;

    // packed neighborhood: lane0 = current image (g_x1), lane1 = prev image (255*x)
    unsigned long long pnb[25];
    {
        const float* img1 = g_x1 + (size_t)b * NN * NN;
        const float* img0 = x + (size_t)b * NN * NN;
        int rr[5], cc[5];
#pragma unroll
        for (int i = 0; i < 5; i++) {
            rr[i] = min(max(p - 2 + i, 0), NN - 1);
            cc[i] = min(max(q - 2 + i, 0), NN - 1);
        }
#pragma unroll
        for (int i = 0; i < 5; i++)
#pragma unroll
            for (int j = 0; j < 5; j++) {
                float v1 = __ldg(img1 + rr[i] * NN + cc[j]);
                float v0 = 255.0f * __ldg(img0 + rr[i] * NN + cc[j]);
                pnb[i * 5 + j] = pack2f(v1, v0);
            }
    }

    float blk[16];
#pragma unroll
    for (int k = 0; k < 16; k++) blk[k] = 0.0f;

#pragma unroll
    for (int s = 0; s < 3; s++) {
        const float* wg = c_samp1 + s * 36;
        const float* bi = c_sb1 + s * 4;
        const uint4* lt = g_q1 + s * LUT_N;

        // ---- paired conv (cur, prev share weights), W2 packs amortized over 4 rotations ----
        float v[4][4];   // [R][ch], blended
#pragma unroll
        for (int ch = 0; ch < 4; ch++) {
            unsigned long long W2[9];
#pragma unroll
            for (int t = 0; t < 9; t++) {
                float wv = wg[ch * 9 + t];
                W2[t] = pack2f(wv, wv);
            }
            float bv = bi[ch];
            unsigned long long B2b = pack2f(bv, bv);
            float rwc = fminf(fmaxf(c_resw[s * 4 + ch], 0.0f), 1.0f);
#pragma unroll
            for (int R = 0; R < 4; R++) {
                unsigned long long a2 = B2b;
#pragma unroll
                for (int u = 0; u < 3; u++)
#pragma unroll
                    for (int w = 0; w < 3; w++)
                        a2 = ffma2(W2[u * 3 + w], pnb[nb_idx(R, u, w)], a2);
                float vc, vp;
                unpack2(a2, vc, vp);
                v[R][ch] = vc + rwc * (vp - vc);
            }
        }

        proc_rot1<0>(v[0], lt, blk);
        proc_rot1<1>(v[1], lt, blk);
        proc_rot1<2>(v[2], lt, blk);
        proc_rot1<3>(v[3], lt, blk);
    }

    float* op = out + ((size_t)b << 22) + (size_t)(4 * p) * 2048 + 4 * q;
#pragma unroll
    for (int i = 0; i < 4; i++) {
        float4 o;
        o.x = rintf(fminf(fmaxf(blk[i * 4 + 0] * (1.0f / 3.0f), 0.0f), 255.0f)) * (1.0f / 255.0f);
        o.y = rintf(fminf(fmaxf(blk[i * 4 + 1] * (1.0f / 3.0f), 0.0f), 255.0f)) * (1.0f / 255.0f);
        o.z = rintf(fminf(fmaxf(blk[i * 4 + 2] * (1.0f / 3.0f), 0.0f), 255.0f)) * (1.0f / 255.0f);
        o.w = rintf(fminf(fmaxf(blk[i * 4 + 3] * (1.0f / 3.0f), 0.0f), 255.0f)) * (1.0f / 255.0f);
        *reinterpret_cast<float4*>(op + (size_t)i * 2048) = o;
    }
}

// ---------------- launch ----------------
extern "C" void kernel_launch(void* const* d_in, const int* in_sizes, int n_in,
                              void* d_out, int out_size) {
    const float* x     = (const float*)d_in[0];
    const float* lut0  = (const float*)d_in[1];
    const float* lut1  = (const float*)d_in[2];
    const float* samp0 = (const float*)d_in[3];
    const float* samp1 = (const float*)d_in[4];
    const float* sb0   = (const float*)d_in[5];
    const float* sb1   = (const float*)d_in[6];
    const float* resw  = (const float*)d_in[7];

    cudaMemcpyToSymbolAsync(c_samp0, samp0, 108 * sizeof(float), 0, cudaMemcpyDeviceToDevice);
    cudaMemcpyToSymbolAsync(c_samp1, samp1, 108 * sizeof(float), 0, cudaMemcpyDeviceToDevice);
    cudaMemcpyToSymbolAsync(c_sb0,   sb0,    12 * sizeof(float), 0, cudaMemcpyDeviceToDevice);
    cudaMemcpyToSymbolAsync(c_sb1,   sb1,    12 * sizeof(float), 0, cudaMemcpyDeviceToDevice);
    cudaMemcpyToSymbolAsync(c_resw,  resw,   12 * sizeof(float), 0, cudaMemcpyDeviceToDevice);

    quant_lut0<<<(3 * LUT_N + 255) / 256, 256>>>(lut0);
    quant_lut1<<<(3 * LUT_N * 4 + 255) / 256, 256>>>(lut1);

    dim3 blk0(32, 8, 1);
    dim3 grd0(NN / 32, NN / 8, 4);
    stage0_kernel<<<grd0, blk0>>>(x);

    dim3 blk1(32, 8, 1);
    dim3 grd1(NN / 32, NN / 8, 4);
    stage1_kernel<<<grd1, blk1>>>(x, (float*)d_out);
}